// round 10
// baseline (speedup 1.0000x reference)
#include <cuda_runtime.h>
#include <cstdint>

#define B_  32
#define S_  2048
#define C_  1024
#define G_  16
#define K_  256
#define REP 4          // replicas per (b,g) row

__device__ float g_norms[B_ * G_ * S_];   // (B*g, S) row-major

// ---------------------------------------------------------------------------
// K1 (fused): sum-of-squares per (b,s,group) AND zero-fill of out.
// 8 bs-rows per block, 256 threads; measured ~6.3-6.7 TB/s aggregate. Final.
// ---------------------------------------------------------------------------
__global__ __launch_bounds__(256) void k_norms_zero(const float* __restrict__ x,
                                                    float* __restrict__ out) {
    const int base_bs = blockIdx.x << 3;
    const int t = threadIdx.x;

    float4 v[8];
    #pragma unroll
    for (int r = 0; r < 8; r++)
        v[r] = reinterpret_cast<const float4*>(
                   x + (size_t)(base_bs + r) * C_)[t];

    const float4 z = make_float4(0.f, 0.f, 0.f, 0.f);
    #pragma unroll
    for (int r = 0; r < 8; r++)
        __stcs(reinterpret_cast<float4*>(
                   out + (size_t)(base_bs + r) * C_) + t, z);

    #pragma unroll
    for (int r = 0; r < 8; r++) {
        float ss = v[r].x * v[r].x + v[r].y * v[r].y
                 + v[r].z * v[r].z + v[r].w * v[r].w;
        #pragma unroll
        for (int off = 8; off > 0; off >>= 1)
            ss += __shfl_down_sync(0xffffffffu, ss, off, 16);
        if ((t & 15) == 0) {
            const int bs = base_bs + r;
            const int b  = bs >> 11;
            const int s  = bs & (S_ - 1);
            g_norms[((b << 4) + (t >> 4)) * S_ + s] = ss;
        }
    }
}

// ---------------------------------------------------------------------------
// K2 (fused select + apply, replicated): REP blocks per (b,g) row. Each
// replica runs the identical 4-pass radix select, builds the CANONICAL
// exact-K list (deterministic: strictly-greater in index order, then ties in
// index order up to K), and copies its 1/REP share of the 256 chunks.
// Determinism across replicas is load-bearing: the list must be identical in
// content AND order, so compaction uses a block scan, never atomics.
// ---------------------------------------------------------------------------
__global__ __launch_bounds__(256) void k_select_apply(const float* __restrict__ x,
                                                      float* __restrict__ out) {
    __shared__ unsigned int vals[S_];
    __shared__ int hist[8][256];
    __shared__ int sh_k;
    __shared__ unsigned int sh_prefix;
    __shared__ int wsum[8];
    __shared__ int sh_ngt;
    __shared__ unsigned short sel[K_];

    const int row = blockIdx.x >> 2;        // b*16 + g
    const int rep = blockIdx.x & (REP - 1);
    const int b   = row >> 4;
    const int g   = row & 15;
    const int tid = threadIdx.x;
    const int w   = tid >> 5;
    const int ln  = tid & 31;
    const float* nr = g_norms + (size_t)row * S_;

    #pragma unroll
    for (int i = tid; i < S_; i += 256)
        vals[i] = __float_as_uint(nr[i]);
    if (tid == 0) { sh_k = K_; sh_prefix = 0u; }
    #pragma unroll
    for (int c = 0; c < 8; c++) hist[c][tid] = 0;
    __syncthreads();

    int k = K_;
    unsigned int prefix = 0u;
    #pragma unroll
    for (int shift = 24; shift >= 0; shift -= 8) {
        if (shift == 24) {
            #pragma unroll
            for (int i = tid; i < S_; i += 256)
                atomicAdd(&hist[w][vals[i] >> 24], 1);
        } else {
            const unsigned int pmask = 0xFFFFFFFFu << (shift + 8);
            #pragma unroll
            for (int i = tid; i < S_; i += 256) {
                const unsigned int u = vals[i];
                if ((u & pmask) == prefix)
                    atomicAdd(&hist[w][(u >> shift) & 255], 1);
            }
        }
        __syncthreads();

        if (tid < 32) {
            const int binbase = 255 - tid * 8;  // lane 0 owns top bins
            int bc[8];
            int c = 0;
            #pragma unroll
            for (int j = 0; j < 8; j++) {
                int h = 0;
                #pragma unroll
                for (int cp = 0; cp < 8; cp++) h += hist[cp][binbase - j];
                bc[j] = h;
                c += h;
            }
            int inc = c;
            #pragma unroll
            for (int off = 1; off < 32; off <<= 1) {
                const int nth = __shfl_up_sync(0xffffffffu, inc, off);
                if (tid >= off) inc += nth;
            }
            const int pre = inc - c;
            const bool hit = (pre < k) && (pre + c >= k);
            const unsigned int bal = __ballot_sync(0xffffffffu, hit);
            if (tid == (__ffs(bal) - 1)) {
                int cum = pre;
                #pragma unroll
                for (int j = 0; j < 8; j++) {
                    if (cum + bc[j] >= k) {
                        sh_k = k - cum;
                        sh_prefix = prefix |
                            ((unsigned int)(binbase - j) << shift);
                        break;
                    }
                    cum += bc[j];
                }
            }
        }
        __syncthreads();
        k = sh_k;
        prefix = sh_prefix;
        if (shift > 0) {
            #pragma unroll
            for (int c = 0; c < 8; c++) hist[c][tid] = 0;
            __syncthreads();
        }
    }

    const float thr = __uint_as_float(prefix);  // exact Kth largest

    // ---- Deterministic canonical compaction (index-ascending) ----
    // Thread t owns contiguous indices [t*8, t*8+8).
    int c1 = 0, c2 = 0;
    float fv[8];
    #pragma unroll
    for (int j = 0; j < 8; j++) {
        fv[j] = __uint_as_float(vals[tid * 8 + j]);
        c1 += (fv[j] > thr) ? 1 : 0;
        c2 += (fv[j] == thr) ? 1 : 0;
    }
    // block exclusive scan of (c1, c2) packed
    int pk = (c1 << 12) | c2;
    int inc = pk;
    #pragma unroll
    for (int off = 1; off < 32; off <<= 1) {
        const int nth = __shfl_up_sync(0xffffffffu, inc, off);
        if (ln >= off) inc += nth;
    }
    if (ln == 31) wsum[w] = inc;
    __syncthreads();
    if (tid < 8) {
        int v8 = wsum[tid];
        int i8 = v8;
        #pragma unroll
        for (int off = 1; off < 8; off <<= 1) {
            const int nth = __shfl_up_sync(0x000000FFu, i8, off);
            if (tid >= off) i8 += nth;
        }
        wsum[tid] = i8 - v8;                 // exclusive warp prefix
        if (tid == 7) sh_ngt = (i8 >> 12);   // block total of c1
    }
    __syncthreads();
    const int ex = inc - pk + wsum[w];       // exclusive prefix for this thread
    const int ngt = sh_ngt;
    const int needed = K_ - ngt;             // >= 1 (thr itself is in-set)
    int r1 = (ex >> 12) & 0xFFF;
    int r2 = ex & 0xFFF;
    #pragma unroll
    for (int j = 0; j < 8; j++) {
        const int i = tid * 8 + j;
        if (fv[j] > thr) {
            sel[r1++] = (unsigned short)i;
        } else if (fv[j] == thr) {
            if (r2 < needed) sel[ngt + r2] = (unsigned short)i;
            r2++;
        }
    }
    __syncthreads();

    // ---- Copy this replica's quarter: slots [rep*64, rep*64+64) ----
    const int sub  = tid >> 4;   // 0..15
    const int lane = tid & 15;   // 0..15
    const float* xb = x   + (size_t)b * S_ * C_ + g * 64;
    float*       ob = out + (size_t)b * S_ * C_ + g * 64;

    int si[4];
    float4 v[4];
    #pragma unroll
    for (int it = 0; it < 4; it++)
        si[it] = sel[rep * 64 + it * 16 + sub];
    #pragma unroll
    for (int it = 0; it < 4; it++)
        v[it] = __ldcs(reinterpret_cast<const float4*>(
                           xb + (size_t)si[it] * C_) + lane);
    #pragma unroll
    for (int it = 0; it < 4; it++)
        reinterpret_cast<float4*>(ob + (size_t)si[it] * C_)[lane] = v[it];
}

extern "C" void kernel_launch(void* const* d_in, const int* in_sizes, int n_in,
                              void* d_out, int out_size) {
    const float* x = (const float*)d_in[0];
    float* out = (float*)d_out;
    k_norms_zero  <<<(B_ * S_) / 8, 256>>>(x, out);
    k_select_apply<<<B_ * G_ * REP, 256>>>(x, out);
}

// round 11
// speedup vs baseline: 1.1401x; 1.1401x over previous
#include <cuda_runtime.h>
#include <cstdint>

#define B_  32
#define S_  2048
#define C_  1024
#define G_  16
#define K_  256

__device__ float g_norms[B_ * G_ * S_];   // (B*g, S) row-major

// ---------------------------------------------------------------------------
// K1 (fused): sum-of-squares per (b,s,group) AND zero-fill of out.
// 8 bs-rows per block, 256 threads. x reads use DEFAULT policy (L2 retains
// recent x for K2's gather); zero stores are streaming (never re-read by L2
// except K2's overwrite which misses anyway). Measured 76.9us. Final.
// ---------------------------------------------------------------------------
__global__ __launch_bounds__(256) void k_norms_zero(const float* __restrict__ x,
                                                    float* __restrict__ out) {
    const int base_bs = blockIdx.x << 3;
    const int t = threadIdx.x;

    float4 v[8];
    #pragma unroll
    for (int r = 0; r < 8; r++)
        v[r] = reinterpret_cast<const float4*>(
                   x + (size_t)(base_bs + r) * C_)[t];

    const float4 z = make_float4(0.f, 0.f, 0.f, 0.f);
    #pragma unroll
    for (int r = 0; r < 8; r++)
        __stcs(reinterpret_cast<float4*>(
                   out + (size_t)(base_bs + r) * C_) + t, z);

    #pragma unroll
    for (int r = 0; r < 8; r++) {
        float ss = v[r].x * v[r].x + v[r].y * v[r].y
                 + v[r].z * v[r].z + v[r].w * v[r].w;
        #pragma unroll
        for (int off = 8; off > 0; off >>= 1)
            ss += __shfl_down_sync(0xffffffffu, ss, off, 16);
        if ((t & 15) == 0) {
            const int bs = base_bs + r;
            const int b  = bs >> 11;
            const int s  = bs & (S_ - 1);
            g_norms[((b << 4) + (t >> 4)) * S_ + s] = ss;
        }
    }
}

// ---------------------------------------------------------------------------
// K2 (fused select + apply), 512 blocks x 256 threads.
// Register-resident select: thread t owns norms [t*8, t*8+8) loaded once as
// two uint4 (no smem vals array). 4-pass radix select with per-warp
// replicated, DOUBLE-BUFFERED histograms (idle buffer zeroed concurrently
// with active pass atomics -> 2 barriers/pass). Deterministic scan-based
// exact-K compaction (index-ascending, ties filled in index order), then
// R7-proven gather copy (16 subgroups x 16 lanes, MLP=8).
// ---------------------------------------------------------------------------
__global__ __launch_bounds__(256) void k_select_apply(const float* __restrict__ x,
                                                      float* __restrict__ out) {
    __shared__ int hist[2][8][256];
    __shared__ int sh_k;
    __shared__ unsigned int sh_prefix;
    __shared__ int wsum[8];
    __shared__ int sh_ngt;
    __shared__ unsigned short sel[K_];

    const int row = blockIdx.x;             // b*16 + g
    const int b   = row >> 4;
    const int g   = row & 15;
    const int tid = threadIdx.x;
    const int w   = tid >> 5;
    const int ln  = tid & 31;

    // Own 8 contiguous norms in registers (coalesced 32B per thread).
    const uint4* nv = reinterpret_cast<const uint4*>(
                          g_norms + (size_t)row * S_) + tid * 2;
    const uint4 a0 = nv[0];
    const uint4 a1 = nv[1];
    unsigned int u[8] = {a0.x, a0.y, a0.z, a0.w, a1.x, a1.y, a1.z, a1.w};

    if (tid == 0) { sh_k = K_; sh_prefix = 0u; }
    #pragma unroll
    for (int c = 0; c < 8; c++) hist[0][c][tid] = 0;
    __syncthreads();

    int k = K_;
    unsigned int prefix = 0u;
    int cur = 0;
    #pragma unroll
    for (int shift = 24; shift >= 0; shift -= 8) {
        // zero the idle buffer while doing this pass's atomics
        #pragma unroll
        for (int c = 0; c < 8; c++) hist[cur ^ 1][c][tid] = 0;

        if (shift == 24) {
            #pragma unroll
            for (int j = 0; j < 8; j++)
                atomicAdd(&hist[cur][w][u[j] >> 24], 1);
        } else {
            const unsigned int pmask = 0xFFFFFFFFu << (shift + 8);
            #pragma unroll
            for (int j = 0; j < 8; j++)
                if ((u[j] & pmask) == prefix)
                    atomicAdd(&hist[cur][w][(u[j] >> shift) & 255], 1);
        }
        __syncthreads();

        if (tid < 32) {
            const int binbase = 255 - tid * 8;  // lane 0 owns top bins
            int bc[8];
            int c = 0;
            #pragma unroll
            for (int j = 0; j < 8; j++) {
                int h = 0;
                #pragma unroll
                for (int cp = 0; cp < 8; cp++)
                    h += hist[cur][cp][binbase - j];
                bc[j] = h;
                c += h;
            }
            int inc = c;
            #pragma unroll
            for (int off = 1; off < 32; off <<= 1) {
                const int nth = __shfl_up_sync(0xffffffffu, inc, off);
                if (tid >= off) inc += nth;
            }
            const int pre = inc - c;
            const bool hit = (pre < k) && (pre + c >= k);
            const unsigned int bal = __ballot_sync(0xffffffffu, hit);
            if (tid == (__ffs(bal) - 1)) {
                int cum = pre;
                #pragma unroll
                for (int j = 0; j < 8; j++) {
                    if (cum + bc[j] >= k) {
                        sh_k = k - cum;
                        sh_prefix = prefix |
                            ((unsigned int)(binbase - j) << shift);
                        break;
                    }
                    cum += bc[j];
                }
            }
        }
        __syncthreads();
        k = sh_k;
        prefix = sh_prefix;
        cur ^= 1;
    }

    const float thr = __uint_as_float(prefix);  // exact Kth largest

    // ---- Deterministic exact-K compaction (index-ascending; R10-proven) ----
    int c1 = 0, c2 = 0;
    float fv[8];
    #pragma unroll
    for (int j = 0; j < 8; j++) {
        fv[j] = __uint_as_float(u[j]);
        c1 += (fv[j] > thr) ? 1 : 0;
        c2 += (fv[j] == thr) ? 1 : 0;
    }
    int pk = (c1 << 12) | c2;
    int inc = pk;
    #pragma unroll
    for (int off = 1; off < 32; off <<= 1) {
        const int nth = __shfl_up_sync(0xffffffffu, inc, off);
        if (ln >= off) inc += nth;
    }
    if (ln == 31) wsum[w] = inc;
    __syncthreads();
    if (tid < 8) {
        int v8 = wsum[tid];
        int i8 = v8;
        #pragma unroll
        for (int off = 1; off < 8; off <<= 1) {
            const int nth = __shfl_up_sync(0x000000FFu, i8, off);
            if (tid >= off) i8 += nth;
        }
        wsum[tid] = i8 - v8;                 // exclusive warp prefix
        if (tid == 7) sh_ngt = (i8 >> 12);   // total strictly-greater
    }
    __syncthreads();
    const int ex  = inc - pk + wsum[w];
    const int ngt = sh_ngt;
    const int needed = K_ - ngt;             // >= 1
    int r1 = (ex >> 12) & 0xFFF;
    int r2 = ex & 0xFFF;
    #pragma unroll
    for (int j = 0; j < 8; j++) {
        const int i = tid * 8 + j;
        if (fv[j] > thr) {
            sel[r1++] = (unsigned short)i;
        } else if (fv[j] == thr) {
            if (r2 < needed) sel[ngt + r2] = (unsigned short)i;
            r2++;
        }
    }
    __syncthreads();

    // ---- Copy the 256 selected 64-channel chunks (R7-proven, MLP=8) ----
    const int sub  = tid >> 4;   // 0..15
    const int lane = tid & 15;   // 0..15
    const float* xb = x   + (size_t)b * S_ * C_ + g * 64;
    float*       ob = out + (size_t)b * S_ * C_ + g * 64;

    #pragma unroll
    for (int half = 0; half < 2; half++) {
        int si[8];
        float4 v[8];
        #pragma unroll
        for (int it = 0; it < 8; it++)
            si[it] = sel[(half * 8 + it) * 16 + sub];
        #pragma unroll
        for (int it = 0; it < 8; it++)
            v[it] = reinterpret_cast<const float4*>(
                        xb + (size_t)si[it] * C_)[lane];
        #pragma unroll
        for (int it = 0; it < 8; it++)
            __stcs(reinterpret_cast<float4*>(
                       ob + (size_t)si[it] * C_) + lane, v[it]);
    }
}

extern "C" void kernel_launch(void* const* d_in, const int* in_sizes, int n_in,
                              void* d_out, int out_size) {
    const float* x = (const float*)d_in[0];
    float* out = (float*)d_out;
    k_norms_zero  <<<(B_ * S_) / 8, 256>>>(x, out);
    k_select_apply<<<B_ * G_, 256>>>(x, out);
}